// round 6
// baseline (speedup 1.0000x reference)
#include <cuda_runtime.h>
#include <cuda_bf16.h>
#include <cstdint>
#include <math.h>

// ---------------- problem constants ----------------
#define LSEQ   4096
#define DM     256
#define DI     512
#define DS     16
#define DTR    16
#define NXP    48
#define NXPAD  64
#define DCONV  4
#define NC     64
#define CLEN   64
#define LN_EPS 1e-5f

// ---------------- device scratch ----------------
__device__ float g_t0  [LSEQ*DM];
__device__ float g_part[4*LSEQ*DM];
__device__ float g_h1  [LSEQ*DM];
__device__ float g_hln [LSEQ*DM];
__device__ float g_xz  [LSEQ*2*DI];
__device__ float g_u   [LSEQ*DI];
__device__ float g_wxpp[DI*NXPAD];
__device__ float g_dbc [LSEQ*NXPAD];
__device__ float g_dt  [LSEQ*DI];
__device__ float g_cP  [NC*DI*DS];
__device__ float g_cS  [NC*DI*DS];
__device__ float g_hin [NC*DI*DS];
__device__ float g_yg  [LSEQ*DI];

// ================= helpers =================
__device__ __forceinline__ uint32_t smem_u32(const void* p) {
    uint32_t a;
    asm("{ .reg .u64 t; cvta.to.shared.u64 t, %1; cvt.u32.u64 %0, t; }" : "=r"(a) : "l"(p));
    return a;
}

#define LDMATRIX_X4(r, addr) \
    asm volatile("ldmatrix.sync.aligned.m8n8.x4.shared.b16 {%0,%1,%2,%3}, [%4];" \
        : "=r"((r)[0]), "=r"((r)[1]), "=r"((r)[2]), "=r"((r)[3]) : "r"(addr))

#define MMA_BF16(c, a, b) \
    asm volatile("mma.sync.aligned.m16n8k16.row.col.f32.bf16.bf16.f32 " \
        "{%0,%1,%2,%3},{%4,%5,%6,%7},{%8,%9},{%0,%1,%2,%3};" \
        : "+f"((c)[0]), "+f"((c)[1]), "+f"((c)[2]), "+f"((c)[3]) \
        : "r"((a)[0]), "r"((a)[1]), "r"((a)[2]), "r"((a)[3]), "r"((b)[0]), "r"((b)[1]))

__device__ __forceinline__ uint32_t pack2(float e0, float e1) {
    __nv_bfloat162 v = __floats2bfloat162_rn(e0, e1);
    return *(uint32_t*)&v;
}
__device__ __forceinline__ void split1(float v, float& hi, float& lo) {
    __nv_bfloat16 h = __float2bfloat16_rn(v);
    hi = __bfloat162float(h);
    lo = v - hi;
}

// ================= bf16x3-split GEMM =================
// C = Ahi*Bhi + Ahi*Blo + Alo*Bhi. Block BMt x 64, BK=32, WM*4 warps
// (WM in M x 4 in N), warp tile 64x16. Two-stage SMEM, one sync/chunk,
// register-staged global loads, split done once at stage time.
#define BN 64
#define BK 32
#define ASTR 40          // b16 per A smem row
#define BSTRW 72         // words per B k2-row

template<int WM, bool BIAS_RELU>
__global__ __launch_bounds__(WM * 128, 2)
void mma_gemm(const float* __restrict__ A, const float* __restrict__ B,
              const float* __restrict__ bias, float* __restrict__ C,
              int K, int Ng, int lda, size_t csplit)
{
    constexpr int NT   = WM * 128;
    constexpr int BMt  = WM * 64;
    constexpr int A_LO = BMt * ASTR * 2;          // bytes per A tile
    constexpr int B_HI = 2 * A_LO;
    constexpr int B_LO = B_HI + 16 * BSTRW * 4;
    constexpr int STAGE = B_LO + 16 * BSTRW * 4;
    constexpr int NB2  = 2 / WM;                  // B float4-pair iters per thread

    extern __shared__ char smem[];
    const uint32_t sb = smem_u32(smem);
    const int tid  = threadIdx.x;
    const int wid  = tid >> 5, lane = tid & 31;
    const int warpM = wid % WM, warpN = wid / WM;
    const int m0 = blockIdx.y * BMt;
    const int n0 = blockIdx.x * BN;
    const int z  = blockIdx.z;
    const int g  = lane >> 2, tg = lane & 3;

    const float* Az = A + (size_t)z * K;
    const float* Bz = B + (size_t)z * K * Ng;
    float*       Cz = C + (size_t)z * csplit;
    const int nch = K / BK;

    const int arow0 = tid >> 3;          // + i*(NT/8)
    const int aseg  = tid & 7;

    float4 ga[4], gb[NB2][2];
    auto ldG = [&](int c) {
        const int k0 = c * BK;
#pragma unroll
        for (int i = 0; i < 4; i++)
            ga[i] = *(const float4*)(Az + (size_t)(m0 + arow0 + (NT / 8) * i) * lda + k0 + aseg * 4);
#pragma unroll
        for (int j = 0; j < NB2; j++) {
            const int q = tid + j * NT;
            const int bk2 = q >> 4, bn4 = (q & 15) * 4;
            gb[j][0] = *(const float4*)(Bz + (size_t)(k0 + 2 * bk2)     * Ng + n0 + bn4);
            gb[j][1] = *(const float4*)(Bz + (size_t)(k0 + 2 * bk2 + 1) * Ng + n0 + bn4);
        }
    };

    auto stS = [&](int s) {
        char* base = smem + s * STAGE;
#pragma unroll
        for (int i = 0; i < 4; i++) {
            const float* e = &ga[i].x;
            float h[4], l[4];
#pragma unroll
            for (int j = 0; j < 4; j++) split1(e[j], h[j], l[j]);
            const uint32_t off = (uint32_t)((arow0 + (NT / 8) * i) * ASTR + aseg * 4) * 2;
            *(uint2*)(base + off)        = make_uint2(pack2(h[0], h[1]), pack2(h[2], h[3]));
            *(uint2*)(base + A_LO + off) = make_uint2(pack2(l[0], l[1]), pack2(l[2], l[3]));
        }
        uint32_t* bh = (uint32_t*)(base + B_HI);
        uint32_t* bl = (uint32_t*)(base + B_LO);
#pragma unroll
        for (int j = 0; j < NB2; j++) {
            const int q = tid + j * NT;
            const int bk2 = q >> 4, bn4 = (q & 15) * 4;
            const float* e0 = &gb[j][0].x;
            const float* e1 = &gb[j][1].x;
#pragma unroll
            for (int jj = 0; jj < 4; jj++) {
                float h0, l0, h1, l1;
                split1(e0[jj], h0, l0);
                split1(e1[jj], h1, l1);
                bh[bk2 * BSTRW + bn4 + jj] = pack2(h0, h1);
                bl[bk2 * BSTRW + bn4 + jj] = pack2(l0, l1);
            }
        }
    };

    float c[4][2][4];
#pragma unroll
    for (int mt = 0; mt < 4; mt++)
#pragma unroll
        for (int nt = 0; nt < 2; nt++)
#pragma unroll
            for (int i = 0; i < 4; i++) c[mt][nt][i] = 0.f;

    const uint32_t aHiOff = (uint32_t)((warpM * 64 + (lane & 15)) * ASTR + (lane >> 4) * 8) * 2;

    ldG(0);
    stS(0);
    for (int ch = 0; ch < nch; ch++) {
        __syncthreads();
        const int st = ch & 1;
        if (ch + 1 < nch) ldG(ch + 1);

        const char* base = smem + st * STAGE;
        const uint32_t aB = sb + st * STAGE + aHiOff;
        const uint32_t* bh = (const uint32_t*)(base + B_HI);
        const uint32_t* bl = (const uint32_t*)(base + B_LO);
#pragma unroll
        for (int kh = 0; kh < 2; kh++) {
            uint32_t bhi[2][2], blo[2][2];
#pragma unroll
            for (int nt = 0; nt < 2; nt++) {
                const int w = (kh * 8 + tg) * BSTRW + warpN * 16 + nt * 8 + g;
                bhi[nt][0] = bh[w];  bhi[nt][1] = bh[w + 4 * BSTRW];
                blo[nt][0] = bl[w];  blo[nt][1] = bl[w + 4 * BSTRW];
            }
#pragma unroll
            for (int mt = 0; mt < 4; mt++) {
                uint32_t ah[4], al[4];
                const uint32_t off = (uint32_t)(mt * 16 * ASTR + kh * 16) * 2;
                LDMATRIX_X4(ah, aB + off);
                LDMATRIX_X4(al, aB + A_LO + off);
#pragma unroll
                for (int nt = 0; nt < 2; nt++) {
                    MMA_BF16(c[mt][nt], ah, bhi[nt]);
                    MMA_BF16(c[mt][nt], ah, blo[nt]);
                    MMA_BF16(c[mt][nt], al, bhi[nt]);
                }
            }
        }
        if (ch + 1 < nch) stS(ch + 1 - ((ch + 1) & 1) ? (ch + 1) & 1 : (ch + 1) & 1);
        if (ch + 1 < nch) { }   // (kept simple below)
        if (ch + 1 < nch) stS((ch + 1) & 1);
    }

    // ---- epilogue ----
#pragma unroll
    for (int mt = 0; mt < 4; mt++)
#pragma unroll
        for (int nt = 0; nt < 2; nt++) {
            const int row = m0 + warpM * 64 + mt * 16 + g;
            const int col = n0 + warpN * 16 + nt * 8 + 2 * tg;
            float2 v0 = make_float2(c[mt][nt][0], c[mt][nt][1]);
            float2 v1 = make_float2(c[mt][nt][2], c[mt][nt][3]);
            if (BIAS_RELU) {
                const float b0 = bias[col], b1 = bias[col + 1];
                v0.x = fmaxf(v0.x + b0, 0.f); v0.y = fmaxf(v0.y + b1, 0.f);
                v1.x = fmaxf(v1.x + b0, 0.f); v1.y = fmaxf(v1.y + b1, 0.f);
            }
            *(float2*)(Cz + (size_t)row * Ng + col)       = v0;
            *(float2*)(Cz + (size_t)(row + 8) * Ng + col) = v1;
        }
}

// ---------------- split-K reduction ----------------
__global__ __launch_bounds__(256)
void reduce_k(const float* __restrict__ p, float* __restrict__ out,
              size_t stride, int count)
{
    const size_t i = ((size_t)blockIdx.x * 256 + threadIdx.x) * 4;
    float4 s = *(const float4*)(p + i);
    for (int cc = 1; cc < count; cc++) {
        float4 v = *(const float4*)(p + cc * stride + i);
        s.x += v.x; s.y += v.y; s.z += v.z; s.w += v.w;
    }
    *(float4*)(out + i) = s;
}

// ---------------- pad w_xp ----------------
__global__ __launch_bounds__(256)
void padw_k(const float* __restrict__ wxp, float* __restrict__ wxpp)
{
    const int i = blockIdx.x * 256 + threadIdx.x;
    const int r = i >> 6, col = i & 63;
    wxpp[i] = (col < NXP) ? wxp[r * NXP + col] : 0.f;
}

// ---------------- layernorm ----------------
__global__ __launch_bounds__(256)
void ln_k(const float* __restrict__ h1, const float* __restrict__ g,
          const float* __restrict__ b, float* __restrict__ out)
{
    const int row = blockIdx.x;
    const int tid = threadIdx.x;
    float v = h1[(size_t)row * DM + tid];
    float s = v, s2 = v * v;
#pragma unroll
    for (int o = 16; o; o >>= 1) {
        s  += __shfl_xor_sync(0xffffffffu, s,  o);
        s2 += __shfl_xor_sync(0xffffffffu, s2, o);
    }
    __shared__ float ws[8], ws2[8];
    if ((tid & 31) == 0) { ws[tid >> 5] = s; ws2[tid >> 5] = s2; }
    __syncthreads();
    float ts = 0.f, ts2 = 0.f;
#pragma unroll
    for (int i = 0; i < 8; i++) { ts += ws[i]; ts2 += ws2[i]; }
    const float mu  = ts * (1.f / DM);
    const float var = ts2 * (1.f / DM) - mu * mu;
    const float r   = rsqrtf(var + LN_EPS);
    out[(size_t)row * DM + tid] = (v - mu) * r * g[tid] + b[tid];
}

// ---------------- conv + silu ----------------
__global__ __launch_bounds__(256)
void conv_silu_k(const float* __restrict__ xz, const float* __restrict__ cw,
                 const float* __restrict__ cb, float* __restrict__ u)
{
    const int idx = blockIdx.x * 256 + threadIdx.x;
    const int l = idx >> 9, d = idx & (DI - 1);
    float s = cb[d];
#pragma unroll
    for (int k = 0; k < DCONV; k++) {
        const int ls = l - (DCONV - 1) + k;
        if (ls >= 0) s += xz[(size_t)ls * (2 * DI) + d] * cw[d * DCONV + k];
    }
    const float sig = 1.f / (1.f + __expf(-s));
    u[idx] = s * sig;
}

// ---------------- dt ----------------
__global__ __launch_bounds__(256)
void dt_k(const float* __restrict__ dbc, const float* __restrict__ wdt,
          const float* __restrict__ bdt, float* __restrict__ dt)
{
    const int idx = blockIdx.x * 256 + threadIdx.x;
    const int l = idx >> 9, d = idx & (DI - 1);
    float s = bdt[d];
    const float* dr = dbc + (size_t)l * NXPAD;
#pragma unroll
    for (int k = 0; k < DTR; k++) s += dr[k] * wdt[k * DI + d];
    dt[idx] = (s > 20.f) ? s : log1pf(__expf(s));
}

// ---------------- scan phase 1 ----------------
__global__ __launch_bounds__(512)
void scan1_k(const float* __restrict__ dt, const float* __restrict__ u,
             const float* __restrict__ dbc, const float* __restrict__ Alog,
             float* __restrict__ cP, float* __restrict__ cS)
{
    const int t = threadIdx.x;
    const int dl = t >> 4, s = t & 15;
    const int d = blockIdx.x * 32 + dl;
    const int c = blockIdx.y;
    const float A = -__expf(Alog[d * DS + s]);
    const int l0 = c * CLEN;
    const float* pdt = dt  + (size_t)l0 * DI + d;
    const float* pu  = u   + (size_t)l0 * DI + d;
    const float* pB  = dbc + (size_t)l0 * NXPAD + DTR + s;
    float P = 1.f, S = 0.f;
#pragma unroll 4
    for (int i = 0; i < CLEN; i++) {
        const float dtv = pdt[i * DI];
        const float uv  = pu [i * DI];
        const float Bv  = pB [i * NXPAD];
        const float a = __expf(A * dtv);
        const float b = dtv * Bv * uv;
        P *= a;
        S = a * S + b;
    }
    const int idx = d * DS + s;
    cP[(size_t)c * (DI * DS) + idx] = P;
    cS[(size_t)c * (DI * DS) + idx] = S;
}

// ---------------- scan phase 2 ----------------
__global__ __launch_bounds__(512)
void scan2_k(const float* __restrict__ cP, const float* __restrict__ cS,
             float* __restrict__ hin)
{
    const int idx = blockIdx.x * 512 + threadIdx.x;
    float h = 0.f;
#pragma unroll 4
    for (int c = 0; c < NC; c++) {
        hin[(size_t)c * (DI * DS) + idx] = h;
        h = cP[(size_t)c * (DI * DS) + idx] * h + cS[(size_t)c * (DI * DS) + idx];
    }
}

// ---------------- scan phase 3 ----------------
__global__ __launch_bounds__(512)
void scan3_k(const float* __restrict__ dt, const float* __restrict__ u,
             const float* __restrict__ dbc, const float* __restrict__ Alog,
             const float* __restrict__ hin, const float* __restrict__ xz,
             const float* __restrict__ Dskip, float* __restrict__ yg)
{
    const int t = threadIdx.x;
    const int dl = t >> 4, s = t & 15;
    const int d = blockIdx.x * 32 + dl;
    const int c = blockIdx.y;
    const float A = -__expf(Alog[d * DS + s]);
    const float Dv = Dskip[d];
    const int l0 = c * CLEN;
    const float* pdt = dt  + (size_t)l0 * DI + d;
    const float* pu  = u   + (size_t)l0 * DI + d;
    const float* pB  = dbc + (size_t)l0 * NXPAD + DTR + s;
    const float* pC  = dbc + (size_t)l0 * NXPAD + DTR + DS + s;
    float h = hin[(size_t)c * (DI * DS) + d * DS + s];
#pragma unroll 2
    for (int i = 0; i < CLEN; i++) {
        const float dtv = pdt[i * DI];
        const float uv  = pu [i * DI];
        const float Bv  = pB [i * NXPAD];
        const float Cv  = pC [i * NXPAD];
        const float a = __expf(A * dtv);
        const float b = dtv * Bv * uv;
        h = a * h + b;
        float p = h * Cv;
        p += __shfl_xor_sync(0xffffffffu, p, 8);
        p += __shfl_xor_sync(0xffffffffu, p, 4);
        p += __shfl_xor_sync(0xffffffffu, p, 2);
        p += __shfl_xor_sync(0xffffffffu, p, 1);
        if (s == 0) {
            const int l = l0 + i;
            const float zv  = xz[(size_t)l * (2 * DI) + DI + d];
            const float sig = 1.f / (1.f + __expf(-zv));
            yg[(size_t)l * DI + d] = (p + uv * Dv) * (zv * sig);
        }
    }
}

// ---------------- host launch ----------------
static float* symaddr(const void* sym)
{
    void* p = nullptr;
    cudaGetSymbolAddress(&p, sym);
    return (float*)p;
}

#define SMEM_OF(WM) (2 * (2 * (WM * 64 * ASTR * 2) + 2 * 16 * BSTRW * 4))

extern "C" void kernel_launch(void* const* d_in, const int* in_sizes, int n_in,
                              void* d_out, int out_size)
{
    const float* x     = (const float*)d_in[0];
    const float* adj   = (const float*)d_in[1];
    const float* gcn_w = (const float*)d_in[2];
    const float* gcn_b = (const float*)d_in[3];
    const float* ln_g  = (const float*)d_in[4];
    const float* ln_b  = (const float*)d_in[5];
    const float* w_in  = (const float*)d_in[6];
    const float* conv_w= (const float*)d_in[7];
    const float* conv_b= (const float*)d_in[8];
    const float* w_xp  = (const float*)d_in[9];
    const float* w_dt  = (const float*)d_in[10];
    const float* b_dt  = (const float*)d_in[11];
    const float* A_log = (const float*)d_in[12];
    const float* D_skip= (const float*)d_in[13];
    const float* w_out = (const float*)d_in[14];
    float* out = (float*)d_out;

    float* t0   = symaddr(g_t0);
    float* part = symaddr(g_part);
    float* h1   = symaddr(g_h1);
    float* hln  = symaddr(g_hln);
    float* xz   = symaddr(g_xz);
    float* u    = symaddr(g_u);
    float* wxpp = symaddr(g_wxpp);
    float* dbc  = symaddr(g_dbc);
    float* dt   = symaddr(g_dt);
    float* cP   = symaddr(g_cP);
    float* cS   = symaddr(g_cS);
    float* hin  = symaddr(g_hin);
    float* yg   = symaddr(g_yg);

    const int smem2 = SMEM_OF(2);
    const int smem1 = SMEM_OF(1);
    cudaFuncSetAttribute(mma_gemm<2, false>, cudaFuncAttributeMaxDynamicSharedMemorySize, smem2);
    cudaFuncSetAttribute(mma_gemm<1, false>, cudaFuncAttributeMaxDynamicSharedMemorySize, smem1);
    cudaFuncSetAttribute(mma_gemm<1, true >, cudaFuncAttributeMaxDynamicSharedMemorySize, smem1);

    // 0) pad w_xp
    padw_k<<<(DI * NXPAD) / 256, 256>>>(w_xp, wxpp);

    // 1) adj @ x, split-K=4 [K=1024 each], BM=128
    mma_gemm<2, false><<<dim3(DM / BN, LSEQ / 128, 4), 256, smem2>>>(
        adj, x, nullptr, part, LSEQ / 4, DM, LSEQ, (size_t)LSEQ * DM);
    reduce_k<<<(LSEQ * DM) / 1024, 256>>>(part, t0, (size_t)LSEQ * DM, 4);

    // 2) h1 = relu(t0 @ gcn_w + b), BM=64 (grid 256)
    mma_gemm<1, true ><<<dim3(DM / BN, LSEQ / 64), 128, smem1>>>(
        t0, gcn_w, gcn_b, h1, DM, DM, DM, 0);
    // 3) layernorm
    ln_k<<<LSEQ, 256>>>(h1, ln_g, ln_b, hln);
    // 4) xz = hln @ w_in, BM=128 (grid 512)
    mma_gemm<2, false><<<dim3((2 * DI) / BN, LSEQ / 128), 256, smem2>>>(
        hln, w_in, nullptr, xz, DM, 2 * DI, DM, 0);
    // 5) u = silu(conv(xc) + b)
    conv_silu_k<<<(LSEQ * DI) / 256, 256>>>(xz, conv_w, conv_b, u);
    // 6) dbc = u @ w_xp (padded), BM=64 split-K=4 (grid 256)
    mma_gemm<1, false><<<dim3(NXPAD / BN, LSEQ / 64, 4), 128, smem1>>>(
        u, wxpp, nullptr, part, DI / 4, NXPAD, DI, (size_t)LSEQ * NXPAD);
    reduce_k<<<(LSEQ * NXPAD) / 1024, 256>>>(part, dbc, (size_t)LSEQ * NXPAD, 4);
    // 7) dt
    dt_k<<<(LSEQ * DI) / 256, 256>>>(dbc, w_dt, b_dt, dt);
    // 8-10) chunked selective scan
    scan1_k<<<dim3(DI / 32, NC), 512>>>(dt, u, dbc, A_log, cP, cS);
    scan2_k<<<(DI * DS) / 512, 512>>>(cP, cS, hin);
    scan3_k<<<dim3(DI / 32, NC), 512>>>(dt, u, dbc, A_log, hin, xz, D_skip, yg);
    // 11) out = yg @ w_out, BM=64 split-K=2 (grid 512)
    mma_gemm<1, false><<<dim3(DM / BN, LSEQ / 64, 2), 128, smem1>>>(
        yg, w_out, nullptr, part, DI / 2, DM, DI, (size_t)LSEQ * DM);
    reduce_k<<<(LSEQ * DM) / 1024, 256>>>(part, out, (size_t)LSEQ * DM, 2);
}

// round 7
// speedup vs baseline: 1.5065x; 1.5065x over previous
#include <cuda_runtime.h>
#include <cuda_bf16.h>
#include <cstdint>
#include <math.h>

// ---------------- problem constants ----------------
#define LSEQ   4096
#define DM     256
#define DI     512
#define DS     16
#define DTR    16
#define NXP    48
#define NXPAD  64
#define DCONV  4
#define NC     64
#define CLEN   64
#define LN_EPS 1e-5f

// ---------------- device scratch ----------------
__device__ float g_t0  [LSEQ*DM];
__device__ float g_part[8*LSEQ*DM];        // split-K partials (max 8 x 1M)
__device__ float g_h1  [LSEQ*DM];
__device__ float g_hln [LSEQ*DM];
__device__ float g_xz  [LSEQ*2*DI];
__device__ float g_u   [LSEQ*DI];
__device__ float g_wxpp[DI*NXPAD];
__device__ float g_dbc [LSEQ*NXPAD];
__device__ float g_dt  [LSEQ*DI];
__device__ float g_cP  [NC*DI*DS];
__device__ float g_cS  [NC*DI*DS];
__device__ float g_hin [NC*DI*DS];
__device__ float g_yg  [LSEQ*DI];

// ================= helpers =================
__device__ __forceinline__ uint32_t smem_u32(const void* p) {
    uint32_t a;
    asm("{ .reg .u64 t; cvta.to.shared.u64 t, %1; cvt.u32.u64 %0, t; }" : "=r"(a) : "l"(p));
    return a;
}

#define LDMATRIX_X4(r, addr) \
    asm volatile("ldmatrix.sync.aligned.m8n8.x4.shared.b16 {%0,%1,%2,%3}, [%4];" \
        : "=r"((r)[0]), "=r"((r)[1]), "=r"((r)[2]), "=r"((r)[3]) : "r"(addr))

#define MMA_BF16(c, a, b) \
    asm volatile("mma.sync.aligned.m16n8k16.row.col.f32.bf16.bf16.f32 " \
        "{%0,%1,%2,%3},{%4,%5,%6,%7},{%8,%9},{%0,%1,%2,%3};" \
        : "+f"((c)[0]), "+f"((c)[1]), "+f"((c)[2]), "+f"((c)[3]) \
        : "r"((a)[0]), "r"((a)[1]), "r"((a)[2]), "r"((a)[3]), "r"((b)[0]), "r"((b)[1]))

__device__ __forceinline__ uint32_t pack2(float e0, float e1) {
    __nv_bfloat162 v = __floats2bfloat162_rn(e0, e1);   // .x = e0 (low 16)
    return *(uint32_t*)&v;
}
__device__ __forceinline__ void split1(float v, float& hi, float& lo) {
    __nv_bfloat16 h = __float2bfloat16_rn(v);
    hi = __bfloat162float(h);
    lo = v - hi;
}

// ================= bf16x3-split GEMM =================
// C = Ahi*Bhi + Ahi*Blo + Alo*Bhi. Block 128x64, BK=32, 8 warps (2M x 4N),
// warp tile 64x16. Double-buffered SMEM, ONE __syncthreads per chunk,
// register-staged global loads, bf16 split done once at stage time.
#define BM 128
#define BN 64
#define BK 32
#define ASTR   40        // b16 elements per A smem row
#define BSTRW  72        // 32-bit words per B k2-row
#define A_LO_OFF (BM*ASTR*2)                 // 10240
#define B_HI_OFF (2*BM*ASTR*2)               // 20480
#define B_LO_OFF (B_HI_OFF + 16*BSTRW*4)     // 25088
#define STAGE_B  (B_LO_OFF + 16*BSTRW*4)     // 29696 bytes per stage
#define MMA_SMEM (2*STAGE_B)                 // 59392

template<bool BIAS_RELU>
__global__ __launch_bounds__(256)
void mma_gemm(const float* __restrict__ A, const float* __restrict__ B,
              const float* __restrict__ bias, float* __restrict__ C,
              int K, int Ng, int lda, size_t csplit)
{
    extern __shared__ char smem[];
    const uint32_t sb = smem_u32(smem);
    const int tid  = threadIdx.x;
    const int wid  = tid >> 5, lane = tid & 31;
    const int warpM = wid & 1, warpN = wid >> 1;
    const int m0 = blockIdx.y * BM;
    const int n0 = blockIdx.x * BN;
    const int z  = blockIdx.z;
    const int g  = lane >> 2, tg = lane & 3;

    const float* Az = A + (size_t)z * K;
    const float* Bz = B + (size_t)z * K * Ng;
    float*       Cz = C + (size_t)z * csplit;
    const int nch = K / BK;

    const int arow0 = tid >> 3;          // + 32*i
    const int aseg  = tid & 7;
    const int bk2   = tid >> 4;          // 0..15
    const int bn4   = (tid & 15) * 4;

    float4 ga[4], gb0, gb1;
    auto ldG = [&](int c) {
        const int k0 = c * BK;
#pragma unroll
        for (int i = 0; i < 4; i++)
            ga[i] = *(const float4*)(Az + (size_t)(m0 + arow0 + 32 * i) * lda + k0 + aseg * 4);
        gb0 = *(const float4*)(Bz + (size_t)(k0 + 2 * bk2)     * Ng + n0 + bn4);
        gb1 = *(const float4*)(Bz + (size_t)(k0 + 2 * bk2 + 1) * Ng + n0 + bn4);
    };

    auto stS = [&](int s) {
        char* base = smem + s * STAGE_B;
#pragma unroll
        for (int i = 0; i < 4; i++) {
            const float* e = &ga[i].x;
            float h[4], l[4];
#pragma unroll
            for (int j = 0; j < 4; j++) split1(e[j], h[j], l[j]);
            const uint32_t off = (uint32_t)((arow0 + 32 * i) * ASTR + aseg * 4) * 2;
            *(uint2*)(base + off)          = make_uint2(pack2(h[0], h[1]), pack2(h[2], h[3]));
            *(uint2*)(base + A_LO_OFF + off) = make_uint2(pack2(l[0], l[1]), pack2(l[2], l[3]));
        }
        const float* e0 = &gb0.x;
        const float* e1 = &gb1.x;
        uint32_t* bh = (uint32_t*)(base + B_HI_OFF);
        uint32_t* bl = (uint32_t*)(base + B_LO_OFF);
#pragma unroll
        for (int j = 0; j < 4; j++) {
            float h0, l0, h1, l1;
            split1(e0[j], h0, l0);
            split1(e1[j], h1, l1);
            bh[bk2 * BSTRW + bn4 + j] = pack2(h0, h1);
            bl[bk2 * BSTRW + bn4 + j] = pack2(l0, l1);
        }
    };

    float c[4][2][4];
#pragma unroll
    for (int mt = 0; mt < 4; mt++)
#pragma unroll
        for (int nt = 0; nt < 2; nt++)
#pragma unroll
            for (int i = 0; i < 4; i++) c[mt][nt][i] = 0.f;

    const uint32_t aHiOff = (uint32_t)((warpM * 64 + (lane & 15)) * ASTR + (lane >> 4) * 8) * 2;

    // prologue: buffer 0 filled and visible
    ldG(0);
    stS(0);
    __syncthreads();

    for (int ch = 0; ch < nch; ch++) {
        const int st = ch & 1;
        if (ch + 1 < nch) ldG(ch + 1);

        const char* base = smem + st * STAGE_B;
        const uint32_t aB = sb + st * STAGE_B + aHiOff;
        const uint32_t* bh = (const uint32_t*)(base + B_HI_OFF);
        const uint32_t* bl = (const uint32_t*)(base + B_LO_OFF);
#pragma unroll
        for (int kh = 0; kh < 2; kh++) {
            uint32_t bhi[2][2], blo[2][2];
#pragma unroll
            for (int nt = 0; nt < 2; nt++) {
                const int w = (kh * 8 + tg) * BSTRW + warpN * 16 + nt * 8 + g;
                bhi[nt][0] = bh[w];  bhi[nt][1] = bh[w + 4 * BSTRW];
                blo[nt][0] = bl[w];  blo[nt][1] = bl[w + 4 * BSTRW];
            }
#pragma unroll
            for (int mt = 0; mt < 4; mt++) {
                uint32_t ah[4], al[4];
                const uint32_t off = (uint32_t)(mt * 16 * ASTR + kh * 16) * 2;
                LDMATRIX_X4(ah, aB + off);
                LDMATRIX_X4(al, aB + A_LO_OFF + off);
#pragma unroll
                for (int nt = 0; nt < 2; nt++) {
                    MMA_BF16(c[mt][nt], ah, bhi[nt]);
                    MMA_BF16(c[mt][nt], ah, blo[nt]);
                    MMA_BF16(c[mt][nt], al, bhi[nt]);
                }
            }
        }
        // stage next chunk into the other buffer (safe: all warps finished
        // reading it at the barrier that ended iteration ch-1)
        if (ch + 1 < nch) stS(st ^ 1);
        __syncthreads();
    }

    // ---- epilogue ----
#pragma unroll
    for (int mt = 0; mt < 4; mt++)
#pragma unroll
        for (int nt = 0; nt < 2; nt++) {
            const int row = m0 + warpM * 64 + mt * 16 + g;
            const int col = n0 + warpN * 16 + nt * 8 + 2 * tg;
            float2 v0 = make_float2(c[mt][nt][0], c[mt][nt][1]);
            float2 v1 = make_float2(c[mt][nt][2], c[mt][nt][3]);
            if (BIAS_RELU) {
                const float b0 = bias[col], b1 = bias[col + 1];
                v0.x = fmaxf(v0.x + b0, 0.f); v0.y = fmaxf(v0.y + b1, 0.f);
                v1.x = fmaxf(v1.x + b0, 0.f); v1.y = fmaxf(v1.y + b1, 0.f);
            }
            *(float2*)(Cz + (size_t)row * Ng + col)       = v0;
            *(float2*)(Cz + (size_t)(row + 8) * Ng + col) = v1;
        }
}

// ---------------- split-K reduction ----------------
__global__ __launch_bounds__(256)
void reduce_k(const float* __restrict__ p, float* __restrict__ out,
              size_t stride, int count)
{
    const size_t i = ((size_t)blockIdx.x * 256 + threadIdx.x) * 4;
    float4 s = *(const float4*)(p + i);
    for (int cc = 1; cc < count; cc++) {
        float4 v = *(const float4*)(p + cc * stride + i);
        s.x += v.x; s.y += v.y; s.z += v.z; s.w += v.w;
    }
    *(float4*)(out + i) = s;
}

// ---------------- pad w_xp 512x48 -> 512x64 ----------------
__global__ __launch_bounds__(256)
void padw_k(const float* __restrict__ wxp, float* __restrict__ wxpp)
{
    const int i = blockIdx.x * 256 + threadIdx.x;
    const int r = i >> 6, col = i & 63;
    wxpp[i] = (col < NXP) ? wxp[r * NXP + col] : 0.f;
}

// ---------------- layernorm ----------------
__global__ __launch_bounds__(256)
void ln_k(const float* __restrict__ h1, const float* __restrict__ g,
          const float* __restrict__ b, float* __restrict__ out)
{
    const int row = blockIdx.x;
    const int tid = threadIdx.x;
    float v = h1[(size_t)row * DM + tid];
    float s = v, s2 = v * v;
#pragma unroll
    for (int o = 16; o; o >>= 1) {
        s  += __shfl_xor_sync(0xffffffffu, s,  o);
        s2 += __shfl_xor_sync(0xffffffffu, s2, o);
    }
    __shared__ float ws[8], ws2[8];
    if ((tid & 31) == 0) { ws[tid >> 5] = s; ws2[tid >> 5] = s2; }
    __syncthreads();
    float ts = 0.f, ts2 = 0.f;
#pragma unroll
    for (int i = 0; i < 8; i++) { ts += ws[i]; ts2 += ws2[i]; }
    const float mu  = ts * (1.f / DM);
    const float var = ts2 * (1.f / DM) - mu * mu;
    const float r   = rsqrtf(var + LN_EPS);
    out[(size_t)row * DM + tid] = (v - mu) * r * g[tid] + b[tid];
}

// ---------------- conv + silu ----------------
__global__ __launch_bounds__(256)
void conv_silu_k(const float* __restrict__ xz, const float* __restrict__ cw,
                 const float* __restrict__ cb, float* __restrict__ u)
{
    const int idx = blockIdx.x * 256 + threadIdx.x;
    const int l = idx >> 9, d = idx & (DI - 1);
    float s = cb[d];
#pragma unroll
    for (int k = 0; k < DCONV; k++) {
        const int ls = l - (DCONV - 1) + k;
        if (ls >= 0) s += xz[(size_t)ls * (2 * DI) + d] * cw[d * DCONV + k];
    }
    const float sig = 1.f / (1.f + __expf(-s));
    u[idx] = s * sig;
}

// ---------------- dt ----------------
__global__ __launch_bounds__(256)
void dt_k(const float* __restrict__ dbc, const float* __restrict__ wdt,
          const float* __restrict__ bdt, float* __restrict__ dt)
{
    const int idx = blockIdx.x * 256 + threadIdx.x;
    const int l = idx >> 9, d = idx & (DI - 1);
    float s = bdt[d];
    const float* dr = dbc + (size_t)l * NXPAD;
#pragma unroll
    for (int k = 0; k < DTR; k++) s += dr[k] * wdt[k * DI + d];
    dt[idx] = (s > 20.f) ? s : log1pf(__expf(s));
}

// ---------------- scan phase 1 ----------------
__global__ __launch_bounds__(512)
void scan1_k(const float* __restrict__ dt, const float* __restrict__ u,
             const float* __restrict__ dbc, const float* __restrict__ Alog,
             float* __restrict__ cP, float* __restrict__ cS)
{
    const int t = threadIdx.x;
    const int dl = t >> 4, s = t & 15;
    const int d = blockIdx.x * 32 + dl;
    const int c = blockIdx.y;
    const float A = -__expf(Alog[d * DS + s]);
    const int l0 = c * CLEN;
    const float* pdt = dt  + (size_t)l0 * DI + d;
    const float* pu  = u   + (size_t)l0 * DI + d;
    const float* pB  = dbc + (size_t)l0 * NXPAD + DTR + s;
    float P = 1.f, S = 0.f;
#pragma unroll 4
    for (int i = 0; i < CLEN; i++) {
        const float dtv = pdt[i * DI];
        const float uv  = pu [i * DI];
        const float Bv  = pB [i * NXPAD];
        const float a = __expf(A * dtv);
        const float b = dtv * Bv * uv;
        P *= a;
        S = a * S + b;
    }
    const int idx = d * DS + s;
    cP[(size_t)c * (DI * DS) + idx] = P;
    cS[(size_t)c * (DI * DS) + idx] = S;
}

// ---------------- scan phase 2 ----------------
__global__ __launch_bounds__(512)
void scan2_k(const float* __restrict__ cP, const float* __restrict__ cS,
             float* __restrict__ hin)
{
    const int idx = blockIdx.x * 512 + threadIdx.x;
    float h = 0.f;
#pragma unroll 4
    for (int c = 0; c < NC; c++) {
        hin[(size_t)c * (DI * DS) + idx] = h;
        h = cP[(size_t)c * (DI * DS) + idx] * h + cS[(size_t)c * (DI * DS) + idx];
    }
}

// ---------------- scan phase 3 ----------------
__global__ __launch_bounds__(512)
void scan3_k(const float* __restrict__ dt, const float* __restrict__ u,
             const float* __restrict__ dbc, const float* __restrict__ Alog,
             const float* __restrict__ hin, const float* __restrict__ xz,
             const float* __restrict__ Dskip, float* __restrict__ yg)
{
    const int t = threadIdx.x;
    const int dl = t >> 4, s = t & 15;
    const int d = blockIdx.x * 32 + dl;
    const int c = blockIdx.y;
    const float A = -__expf(Alog[d * DS + s]);
    const float Dv = Dskip[d];
    const int l0 = c * CLEN;
    const float* pdt = dt  + (size_t)l0 * DI + d;
    const float* pu  = u   + (size_t)l0 * DI + d;
    const float* pB  = dbc + (size_t)l0 * NXPAD + DTR + s;
    const float* pC  = dbc + (size_t)l0 * NXPAD + DTR + DS + s;
    float h = hin[(size_t)c * (DI * DS) + d * DS + s];
#pragma unroll 2
    for (int i = 0; i < CLEN; i++) {
        const float dtv = pdt[i * DI];
        const float uv  = pu [i * DI];
        const float Bv  = pB [i * NXPAD];
        const float Cv  = pC [i * NXPAD];
        const float a = __expf(A * dtv);
        const float b = dtv * Bv * uv;
        h = a * h + b;
        float p = h * Cv;
        p += __shfl_xor_sync(0xffffffffu, p, 8);
        p += __shfl_xor_sync(0xffffffffu, p, 4);
        p += __shfl_xor_sync(0xffffffffu, p, 2);
        p += __shfl_xor_sync(0xffffffffu, p, 1);
        if (s == 0) {
            const int l = l0 + i;
            const float zv  = xz[(size_t)l * (2 * DI) + DI + d];
            const float sig = 1.f / (1.f + __expf(-zv));
            yg[(size_t)l * DI + d] = (p + uv * Dv) * (zv * sig);
        }
    }
}

// ---------------- host launch ----------------
static float* symaddr(const void* sym)
{
    void* p = nullptr;
    cudaGetSymbolAddress(&p, sym);
    return (float*)p;
}

extern "C" void kernel_launch(void* const* d_in, const int* in_sizes, int n_in,
                              void* d_out, int out_size)
{
    const float* x     = (const float*)d_in[0];
    const float* adj   = (const float*)d_in[1];
    const float* gcn_w = (const float*)d_in[2];
    const float* gcn_b = (const float*)d_in[3];
    const float* ln_g  = (const float*)d_in[4];
    const float* ln_b  = (const float*)d_in[5];
    const float* w_in  = (const float*)d_in[6];
    const float* conv_w= (const float*)d_in[7];
    const float* conv_b= (const float*)d_in[8];
    const float* w_xp  = (const float*)d_in[9];
    const float* w_dt  = (const float*)d_in[10];
    const float* b_dt  = (const float*)d_in[11];
    const float* A_log = (const float*)d_in[12];
    const float* D_skip= (const float*)d_in[13];
    const float* w_out = (const float*)d_in[14];
    float* out = (float*)d_out;

    float* t0   = symaddr(g_t0);
    float* part = symaddr(g_part);
    float* h1   = symaddr(g_h1);
    float* hln  = symaddr(g_hln);
    float* xz   = symaddr(g_xz);
    float* u    = symaddr(g_u);
    float* wxpp = symaddr(g_wxpp);
    float* dbc  = symaddr(g_dbc);
    float* dt   = symaddr(g_dt);
    float* cP   = symaddr(g_cP);
    float* cS   = symaddr(g_cS);
    float* hin  = symaddr(g_hin);
    float* yg   = symaddr(g_yg);

    cudaFuncSetAttribute(mma_gemm<false>, cudaFuncAttributeMaxDynamicSharedMemorySize, MMA_SMEM);
    cudaFuncSetAttribute(mma_gemm<true >, cudaFuncAttributeMaxDynamicSharedMemorySize, MMA_SMEM);

    // 0) pad w_xp
    padw_k<<<(DI * NXPAD) / 256, 256>>>(w_xp, wxpp);

    // 1) adj @ x, split-K=8 [K=512 each] -> grid 1024
    mma_gemm<false><<<dim3(DM / BN, LSEQ / BM, 8), 256, MMA_SMEM>>>(
        adj, x, nullptr, part, LSEQ / 8, DM, LSEQ, (size_t)LSEQ * DM);
    reduce_k<<<(LSEQ * DM) / 1024, 256>>>(part, t0, (size_t)LSEQ * DM, 8);

    // 2) h1 = relu(t0 @ gcn_w + b), split-K=2 -> grid 256  (bias+relu only on z=0;
    //    partials summed afterwards would break relu, so keep bias in GEMM only when
    //    no split: do plain split then fused bias+relu in reduce? simplest: split-K=2
    //    WITHOUT bias, then reduce adds bias+relu via dedicated kernel)
    mma_gemm<false><<<dim3(DM / BN, LSEQ / BM, 2), 256, MMA_SMEM>>>(
        t0, gcn_w, nullptr, part, DM / 2, DM, DM, (size_t)LSEQ * DM);
    // fused reduce + bias + relu (count=2)
    {
        // reuse reduce_k then ln? need bias+relu: small dedicated pass below
    }
    // custom: sum 2 partials + bias + relu into h1
    // (implemented inline as a lambda-style kernel launch)
    extern __global__ void gcnfin_k(const float*, const float*, float*);
    gcnfin_k<<<(LSEQ * DM) / 1024, 256>>>(part, gcn_b, h1);

    // 3) layernorm
    ln_k<<<LSEQ, 256>>>(h1, ln_g, ln_b, hln);
    // 4) xz = hln @ w_in (grid 512)
    mma_gemm<false><<<dim3((2 * DI) / BN, LSEQ / BM), 256, MMA_SMEM>>>(
        hln, w_in, nullptr, xz, DM, 2 * DI, DM, 0);
    // 5) u = silu(conv(xc) + b)
    conv_silu_k<<<(LSEQ * DI) / 256, 256>>>(xz, conv_w, conv_b, u);
    // 6) dbc = u @ w_xp (padded), split-K=8 [K=64 each] -> grid 256
    mma_gemm<false><<<dim3(NXPAD / BN, LSEQ / BM, 8), 256, MMA_SMEM>>>(
        u, wxpp, nullptr, part, DI / 8, NXPAD, DI, (size_t)LSEQ * NXPAD);
    reduce_k<<<(LSEQ * NXPAD) / 1024, 256>>>(part, dbc, (size_t)LSEQ * NXPAD, 8);
    // 7) dt
    dt_k<<<(LSEQ * DI) / 256, 256>>>(dbc, w_dt, b_dt, dt);
    // 8-10) chunked selective scan
    scan1_k<<<dim3(DI / 32, NC), 512>>>(dt, u, dbc, A_log, cP, cS);
    scan2_k<<<(DI * DS) / 512, 512>>>(cP, cS, hin);
    scan3_k<<<dim3(DI / 32, NC), 512>>>(dt, u, dbc, A_log, hin, xz, D_skip, yg);
    // 11) out = yg @ w_out, split-K=4 -> grid 512
    mma_gemm<false><<<dim3(DM / BN, LSEQ / BM, 4), 256, MMA_SMEM>>>(
        yg, w_out, nullptr, part, DI / 4, DM, DI, (size_t)LSEQ * DM);
    reduce_k<<<(LSEQ * DM) / 1024, 256>>>(part, out, (size_t)LSEQ * DM, 4);
}

// ---------------- gcn finish: h1 = relu(part0 + part1 + bias) ----------------
__global__ __launch_bounds__(256)
void gcnfin_k(const float* __restrict__ p, const float* __restrict__ bias,
              float* __restrict__ h1)
{
    const size_t i = ((size_t)blockIdx.x * 256 + threadIdx.x) * 4;
    const int col = (int)(i & (DM - 1));
    float4 a = *(const float4*)(p + i);
    float4 b = *(const float4*)(p + (size_t)LSEQ * DM + i);
    float4 o;
    o.x = fmaxf(a.x + b.x + bias[col],     0.f);
    o.y = fmaxf(a.y + b.y + bias[col + 1], 0.f);
    o.z = fmaxf(a.z + b.z + bias[col + 2], 0.f);
    o.w = fmaxf(a.w + b.w + bias[col + 3], 0.f);
    *(float4*)(h1 + i) = o;
}